// round 2
// baseline (speedup 1.0000x reference)
#include <cuda_runtime.h>
#include <cstddef>

#define N_USER  100000
#define N_ITEM  50000
#define N_NODES 150000
#define EMB     64
#define N_EDGES 4000000
#define BATCH   4096
#define PW_INV_LAYERS 0.25f   // 1/(N_LAYERS+1)

// Node-feature scratch (allocation-free: __device__ globals). 38.4 MB each.
__device__ float g_bufA[(size_t)N_NODES * EMB];
__device__ float g_bufB[(size_t)N_NODES * EMB];
__device__ float g_acc [(size_t)N_NODES * EMB];

// ---------------------------------------------------------------------------
// init: bufA = acc = concat(user_emb, item_emb); bufB = 0 (first scatter dst)
// ---------------------------------------------------------------------------
__global__ void lgcn_init(const float* __restrict__ ue,
                          const float* __restrict__ ie) {
    int i = blockIdx.x * blockDim.x + threadIdx.x;   // float4 index
    if (i >= N_NODES * 16) return;
    const float4* u4 = (const float4*)ue;
    const float4* i4 = (const float4*)ie;
    float4 v = (i < N_USER * 16) ? u4[i] : i4[i - N_USER * 16];
    ((float4*)g_bufA)[i] = v;
    ((float4*)g_acc )[i] = v;
    ((float4*)g_bufB)[i] = make_float4(0.f, 0.f, 0.f, 0.f);
}

// ---------------------------------------------------------------------------
// edge pass: dst[row] += val * src[col]
// 16 threads per edge, one float4 (16B) each; scatter with vector RED
// (red.global.add.v4.f32, sm_90+).
// ---------------------------------------------------------------------------
__global__ void lgcn_edge(const int*   __restrict__ rows,
                          const int*   __restrict__ cols,
                          const float* __restrict__ vals,
                          const float* __restrict__ src,
                          float*       __restrict__ dst) {
    unsigned gid = blockIdx.x * blockDim.x + threadIdx.x;
    unsigned e = gid >> 4;
    if (e >= N_EDGES) return;
    unsigned p = gid & 15u;

    int   c = __ldg(cols + e);
    int   r = __ldg(rows + e);
    float v = __ldg(vals + e);

    float4 x = *(const float4*)(src + (size_t)c * EMB + p * 4);
    x.x *= v; x.y *= v; x.z *= v; x.w *= v;

    float* d = dst + (size_t)r * EMB + p * 4;
    asm volatile("red.global.add.v4.f32 [%0], {%1, %2, %3, %4};"
                 :: "l"(d), "f"(x.x), "f"(x.y), "f"(x.z), "f"(x.w)
                 : "memory");
}

// ---------------------------------------------------------------------------
// post pass (fused, no copy-back):
//   t = cur[i] * (apply_pop ? pop_inv[row] : 1)
//   if (apply_pop) cur[i] = t          (next layer reads the scaled value)
//   acc[i] += pw * t
//   if (do_zero)  zbuf[i] = 0          (clean scatter target for next layer)
// cur stays in place; buffers swap roles on the host side.
// ---------------------------------------------------------------------------
__global__ void lgcn_post(float* __restrict__ cur,
                          float* __restrict__ zbuf,
                          const float* __restrict__ upi,
                          const float* __restrict__ ipi,
                          const float* __restrict__ pwp,
                          int apply_pop, int do_zero) {
    int i = blockIdx.x * blockDim.x + threadIdx.x;   // float4 index
    if (i >= N_NODES * 16) return;
    int row = i >> 4;

    float pw = __ldg(pwp);
    float4 t = ((float4*)cur)[i];
    if (apply_pop) {
        float s = (row < N_USER) ? __ldg(upi + row) : __ldg(ipi + (row - N_USER));
        t.x *= s; t.y *= s; t.z *= s; t.w *= s;
        ((float4*)cur)[i] = t;
    }

    float4 a = ((float4*)g_acc)[i];
    a.x = fmaf(pw, t.x, a.x);
    a.y = fmaf(pw, t.y, a.y);
    a.z = fmaf(pw, t.z, a.z);
    a.w = fmaf(pw, t.w, a.w);
    ((float4*)g_acc)[i] = a;

    if (do_zero)
        ((float4*)zbuf)[i] = make_float4(0.f, 0.f, 0.f, 0.f);
}

// ---------------------------------------------------------------------------
// gather: 6 output blocks of [BATCH, EMB] in tuple order:
//   0: acc[users]*0.25  1: acc[N_USER+pos]*0.25  2: acc[N_USER+neg]*0.25
//   3: user_emb[users]  4: item_emb[pos]         5: item_emb[neg]
// ---------------------------------------------------------------------------
__global__ void lgcn_gather(const float* __restrict__ ue,
                            const float* __restrict__ ie,
                            const int*   __restrict__ users,
                            const int*   __restrict__ pos,
                            const int*   __restrict__ neg,
                            float* __restrict__ out) {
    int gid = blockIdx.x * blockDim.x + threadIdx.x;   // float4 index
    const int per_sec = BATCH * 16;
    if (gid >= 6 * per_sec) return;
    int sec = gid / per_sec;
    int rem = gid - sec * per_sec;
    int b = rem >> 4;
    int p = rem & 15;

    const float* src;
    float sc;
    switch (sec) {
        case 0:  src = g_acc + (size_t)__ldg(users + b) * EMB;            sc = PW_INV_LAYERS; break;
        case 1:  src = g_acc + ((size_t)N_USER + __ldg(pos + b)) * EMB;   sc = PW_INV_LAYERS; break;
        case 2:  src = g_acc + ((size_t)N_USER + __ldg(neg + b)) * EMB;   sc = PW_INV_LAYERS; break;
        case 3:  src = ue + (size_t)__ldg(users + b) * EMB;               sc = 1.0f; break;
        case 4:  src = ie + (size_t)__ldg(pos + b) * EMB;                 sc = 1.0f; break;
        default: src = ie + (size_t)__ldg(neg + b) * EMB;                 sc = 1.0f; break;
    }
    float4 v = ((const float4*)src)[p];
    v.x *= sc; v.y *= sc; v.z *= sc; v.w *= sc;
    ((float4*)out)[gid] = v;
}

// ---------------------------------------------------------------------------
// kernel_launch
// Inputs: user_emb, item_emb, edge_rows, edge_cols, edge_vals,
//         user_pop_inv, item_pop_inv, popularity_weight, users, pos, neg
// ---------------------------------------------------------------------------
extern "C" void kernel_launch(void* const* d_in, const int* in_sizes, int n_in,
                              void* d_out, int out_size) {
    const float* ue    = (const float*)d_in[0];
    const float* ie    = (const float*)d_in[1];
    const int*   erow  = (const int*)  d_in[2];
    const int*   ecol  = (const int*)  d_in[3];
    const float* eval_ = (const float*)d_in[4];
    const float* upi   = (const float*)d_in[5];
    const float* ipi   = (const float*)d_in[6];
    const float* pwp   = (const float*)d_in[7];
    const int*   users = (const int*)  d_in[8];
    const int*   pos   = (const int*)  d_in[9];
    const int*   neg   = (const int*)  d_in[10];
    float* out = (float*)d_out;

    // Resolve device-global addresses (host side, graph-capture safe).
    float *bufA, *bufB;
    cudaGetSymbolAddress((void**)&bufA, g_bufA);
    cudaGetSymbolAddress((void**)&bufB, g_bufB);

    const int TB = 256;
    const int node_f4   = N_NODES * 16;                      // 2.4M
    const int node_grid = (node_f4 + TB - 1) / TB;
    const long long edge_threads = (long long)N_EDGES * 16;  // 64M
    const int edge_grid = (int)((edge_threads + TB - 1) / TB);
    const int gath_f4   = 6 * BATCH * 16;
    const int gath_grid = (gath_f4 + TB - 1) / TB;

    lgcn_init<<<node_grid, TB>>>(ue, ie);

    float* cur = bufA;   // holds embeddings
    float* nxt = bufB;   // zeroed scatter target
    for (int k = 0; k < 3; k++) {
        lgcn_edge<<<edge_grid, TB>>>(erow, ecol, eval_, cur, nxt);
        // nxt now holds layer-k output; zero old cur as next scatter target
        lgcn_post<<<node_grid, TB>>>(nxt, cur, upi, ipi, pwp,
                                     (k == 0) ? 1 : 0,
                                     (k < 2) ? 1 : 0);
        float* t = cur; cur = nxt; nxt = t;
    }
    lgcn_gather<<<gath_grid, TB>>>(ue, ie, users, pos, neg, out);

    (void)in_sizes; (void)n_in; (void)out_size;
}

// round 3
// speedup vs baseline: 2.0119x; 2.0119x over previous
#include <cuda_runtime.h>
#include <cstddef>

#define N_USER  100000
#define N_ITEM  50000
#define N_NODES 150000
#define EMB     64
#define N_EDGES 4000000
#define BATCH   4096
#define PW_INV_LAYERS 0.25f   // 1/(N_LAYERS+1)
#define TB 256
#define NBLK ((N_NODES + TB - 1) / TB)   // 586 scan blocks

// ---- device-global scratch (allocation-free) ----
__device__ float g_cur [(size_t)N_NODES * EMB];   // 38.4 MB
__device__ float g_nxt [(size_t)N_NODES * EMB];   // 38.4 MB
__device__ float g_acc [(size_t)N_NODES * EMB];   // 38.4 MB
__device__ int   g_cnt   [N_NODES];
__device__ int   g_fill  [N_NODES];
__device__ int   g_rowptr[N_NODES + 1];
__device__ int   g_bsum  [1024];
__device__ int2  g_perm  [N_EDGES];               // (col, val-as-int) 32 MB

// ---------------------------------------------------------------------------
// init: cur = acc = concat(user_emb, item_emb); cnt = 0
// ---------------------------------------------------------------------------
__global__ void k_init(const float* __restrict__ ue,
                       const float* __restrict__ ie) {
    int i = blockIdx.x * blockDim.x + threadIdx.x;   // float4 index
    if (i < N_NODES) g_cnt[i] = 0;
    if (i >= N_NODES * 16) return;
    const float4* u4 = (const float4*)ue;
    const float4* i4 = (const float4*)ie;
    float4 v = (i < N_USER * 16) ? u4[i] : i4[i - N_USER * 16];
    ((float4*)g_cur)[i] = v;
    ((float4*)g_acc)[i] = v;
}

// ---------------------------------------------------------------------------
// CSR build step 1: histogram of destination rows
// ---------------------------------------------------------------------------
__global__ void k_hist(const int* __restrict__ rows) {
    int e = blockIdx.x * blockDim.x + threadIdx.x;
    if (e >= N_EDGES) return;
    atomicAdd(&g_cnt[__ldg(rows + e)], 1);
}

// ---------------------------------------------------------------------------
// CSR build step 2a: per-block sums of counts
// ---------------------------------------------------------------------------
__global__ void k_scan1() {
    __shared__ int sh[TB];
    int i = blockIdx.x * TB + threadIdx.x;
    int c = (i < N_NODES) ? g_cnt[i] : 0;
    sh[threadIdx.x] = c; __syncthreads();
    for (int off = TB / 2; off > 0; off >>= 1) {
        if (threadIdx.x < off) sh[threadIdx.x] += sh[threadIdx.x + off];
        __syncthreads();
    }
    if (threadIdx.x == 0) g_bsum[blockIdx.x] = sh[0];
}

// ---------------------------------------------------------------------------
// CSR build step 2b: exclusive scan of the 586 block sums (single block)
// ---------------------------------------------------------------------------
__global__ void k_scan2() {
    __shared__ int sh[1024];
    int t = threadIdx.x;
    int v = (t < NBLK) ? g_bsum[t] : 0;
    sh[t] = v; __syncthreads();
    for (int off = 1; off < 1024; off <<= 1) {
        int add = (t >= off) ? sh[t - off] : 0;
        __syncthreads();
        sh[t] += add;
        __syncthreads();
    }
    if (t < NBLK) g_bsum[t] = sh[t] - v;   // exclusive
}

// ---------------------------------------------------------------------------
// CSR build step 2c: per-block exclusive scan + base -> row_ptr, fill cursors
// ---------------------------------------------------------------------------
__global__ void k_scan3() {
    __shared__ int sh[TB];
    int i = blockIdx.x * TB + threadIdx.x;
    int c = (i < N_NODES) ? g_cnt[i] : 0;
    sh[threadIdx.x] = c; __syncthreads();
    for (int off = 1; off < TB; off <<= 1) {
        int add = (threadIdx.x >= off) ? sh[threadIdx.x - off] : 0;
        __syncthreads();
        sh[threadIdx.x] += add;
        __syncthreads();
    }
    int excl = sh[threadIdx.x] - c + g_bsum[blockIdx.x];
    if (i < N_NODES) { g_rowptr[i] = excl; g_fill[i] = excl; }
    if (i == 0) g_rowptr[N_NODES] = N_EDGES;
}

// ---------------------------------------------------------------------------
// CSR build step 3: permute (col, val) into row-grouped order
// ---------------------------------------------------------------------------
__global__ void k_permute(const int*   __restrict__ rows,
                          const int*   __restrict__ cols,
                          const float* __restrict__ vals) {
    int e = blockIdx.x * blockDim.x + threadIdx.x;
    if (e >= N_EDGES) return;
    int r = __ldg(rows + e);
    int idx = atomicAdd(&g_fill[r], 1);
    g_perm[idx] = make_int2(__ldg(cols + e), __float_as_int(__ldg(vals + e)));
}

// ---------------------------------------------------------------------------
// layer (fused SpMM + post): one warp per row.
//   t[row] = sum_{e in row} val_e * src[col_e]        (register accumulation)
//   if APPLY_POP: t *= pop_inv[row]
//   dst[row] = t;  acc[row] += pw * t
// Each lane owns a float2 (32 x 8B = 256B row). No atomics anywhere.
// ---------------------------------------------------------------------------
template <int APPLY_POP>
__global__ void k_layer(const float* __restrict__ src,
                        float*       __restrict__ dst,
                        const float* __restrict__ upi,
                        const float* __restrict__ ipi,
                        const float* __restrict__ pwp) {
    int gid  = blockIdx.x * blockDim.x + threadIdx.x;
    int row  = gid >> 5;
    int lane = gid & 31;
    if (row >= N_NODES) return;

    int beg = __ldg(&g_rowptr[row]);
    int end = __ldg(&g_rowptr[row + 1]);

    float2 s = make_float2(0.f, 0.f);
    for (int base = beg; base < end; base += 32) {
        int n = min(32, end - base);
        int2 ev = make_int2(0, 0);
        if (lane < n) ev = g_perm[base + lane];
        for (int j = 0; j < n; j++) {
            int   c = __shfl_sync(0xffffffffu, ev.x, j);
            float v = __int_as_float(__shfl_sync(0xffffffffu, ev.y, j));
            float2 x = *(const float2*)(src + (size_t)c * EMB + lane * 2);
            s.x = fmaf(v, x.x, s.x);
            s.y = fmaf(v, x.y, s.y);
        }
    }

    if (APPLY_POP) {
        float sc = (row < N_USER) ? __ldg(upi + row) : __ldg(ipi + (row - N_USER));
        s.x *= sc; s.y *= sc;
    }

    float pw = __ldg(pwp);
    float* dp = dst + (size_t)row * EMB + lane * 2;
    *(float2*)dp = s;

    float* ap = g_acc + (size_t)row * EMB + lane * 2;
    float2 a = *(float2*)ap;
    a.x = fmaf(pw, s.x, a.x);
    a.y = fmaf(pw, s.y, a.y);
    *(float2*)ap = a;
}

// ---------------------------------------------------------------------------
// gather: 6 output blocks of [BATCH, EMB] in tuple order.
// ---------------------------------------------------------------------------
__global__ void k_gather(const float* __restrict__ ue,
                         const float* __restrict__ ie,
                         const int*   __restrict__ users,
                         const int*   __restrict__ pos,
                         const int*   __restrict__ neg,
                         float* __restrict__ out) {
    int gid = blockIdx.x * blockDim.x + threadIdx.x;   // float4 index
    const int per_sec = BATCH * 16;
    if (gid >= 6 * per_sec) return;
    int sec = gid / per_sec;
    int rem = gid - sec * per_sec;
    int b = rem >> 4;
    int p = rem & 15;

    const float* src;
    float sc;
    switch (sec) {
        case 0:  src = g_acc + (size_t)__ldg(users + b) * EMB;            sc = PW_INV_LAYERS; break;
        case 1:  src = g_acc + ((size_t)N_USER + __ldg(pos + b)) * EMB;   sc = PW_INV_LAYERS; break;
        case 2:  src = g_acc + ((size_t)N_USER + __ldg(neg + b)) * EMB;   sc = PW_INV_LAYERS; break;
        case 3:  src = ue + (size_t)__ldg(users + b) * EMB;               sc = 1.0f; break;
        case 4:  src = ie + (size_t)__ldg(pos + b) * EMB;                 sc = 1.0f; break;
        default: src = ie + (size_t)__ldg(neg + b) * EMB;                 sc = 1.0f; break;
    }
    float4 v = ((const float4*)src)[p];
    v.x *= sc; v.y *= sc; v.z *= sc; v.w *= sc;
    ((float4*)out)[gid] = v;
}

// ---------------------------------------------------------------------------
// kernel_launch
// Inputs: user_emb, item_emb, edge_rows, edge_cols, edge_vals,
//         user_pop_inv, item_pop_inv, popularity_weight, users, pos, neg
// ---------------------------------------------------------------------------
extern "C" void kernel_launch(void* const* d_in, const int* in_sizes, int n_in,
                              void* d_out, int out_size) {
    const float* ue    = (const float*)d_in[0];
    const float* ie    = (const float*)d_in[1];
    const int*   erow  = (const int*)  d_in[2];
    const int*   ecol  = (const int*)  d_in[3];
    const float* eval_ = (const float*)d_in[4];
    const float* upi   = (const float*)d_in[5];
    const float* ipi   = (const float*)d_in[6];
    const float* pwp   = (const float*)d_in[7];
    const int*   users = (const int*)  d_in[8];
    const int*   pos   = (const int*)  d_in[9];
    const int*   neg   = (const int*)  d_in[10];
    float* out = (float*)d_out;

    float *cur, *nxt;
    cudaGetSymbolAddress((void**)&cur, g_cur);
    cudaGetSymbolAddress((void**)&nxt, g_nxt);

    const int node_f4_grid = (N_NODES * 16 + TB - 1) / TB;
    const int edge_grid    = (N_EDGES + TB - 1) / TB;
    const int row_warp_grid = (N_NODES * 32 + TB - 1) / TB;   // 1 warp/row
    const int gath_grid    = (6 * BATCH * 16 + TB - 1) / TB;

    // init + CSR build (every replay; deterministic work)
    k_init<<<node_f4_grid, TB>>>(ue, ie);
    k_hist<<<edge_grid, TB>>>(erow);
    k_scan1<<<NBLK, TB>>>();
    k_scan2<<<1, 1024>>>();
    k_scan3<<<NBLK, TB>>>();
    k_permute<<<edge_grid, TB>>>(erow, ecol, eval_);

    // 3 propagation layers, atomic-free
    k_layer<1><<<row_warp_grid, TB>>>(cur, nxt, upi, ipi, pwp);
    k_layer<0><<<row_warp_grid, TB>>>(nxt, cur, upi, ipi, pwp);
    k_layer<0><<<row_warp_grid, TB>>>(cur, nxt, upi, ipi, pwp);

    k_gather<<<gath_grid, TB>>>(ue, ie, users, pos, neg, out);

    (void)in_sizes; (void)n_in; (void)out_size;
}

// round 4
// speedup vs baseline: 2.3237x; 1.1550x over previous
#include <cuda_runtime.h>
#include <cuda_fp16.h>
#include <cstddef>

#define N_USER  100000
#define N_ITEM  50000
#define N_NODES 150000
#define EMB     64
#define N_EDGES 4000000
#define BATCH   4096
#define PW_INV_LAYERS 0.25f   // 1/(N_LAYERS+1)
#define TB 256
#define NBLK ((N_NODES + TB - 1) / TB)   // 586 scan blocks

// ---- device-global scratch (allocation-free) ----
// fp16 feature buffers: 150000*64*2B = 19.2 MB each
__device__ __half g_c0[(size_t)N_NODES * EMB];
__device__ __half g_c1[(size_t)N_NODES * EMB];
__device__ __half g_c2[(size_t)N_NODES * EMB];
__device__ __half g_c3[(size_t)N_NODES * EMB];
__device__ int    g_cnt   [N_NODES];
__device__ int    g_fill  [N_NODES];
__device__ int    g_rowptr[N_NODES + 1];
__device__ int    g_bsum  [1024];
__device__ int    g_pcol  [N_EDGES];   // 16 MB
__device__ __half g_pval  [N_EDGES];   //  8 MB

// ---------------------------------------------------------------------------
// init: c0 = fp16(concat(user_emb, item_emb)); cnt = 0
// one thread per half2 (2 floats) -> 4.8M threads
// ---------------------------------------------------------------------------
__global__ void k_init(const float* __restrict__ ue,
                       const float* __restrict__ ie) {
    int i = blockIdx.x * blockDim.x + threadIdx.x;   // float2 index
    if (i < N_NODES) g_cnt[i] = 0;
    if (i >= N_NODES * 32) return;
    const float2* u2 = (const float2*)ue;
    const float2* i2 = (const float2*)ie;
    float2 v = (i < N_USER * 32) ? u2[i] : i2[i - N_USER * 32];
    ((half2*)g_c0)[i] = __floats2half2_rn(v.x, v.y);
}

// ---------------------------------------------------------------------------
// CSR build step 1: histogram of destination rows
// ---------------------------------------------------------------------------
__global__ void k_hist(const int* __restrict__ rows) {
    int e = blockIdx.x * blockDim.x + threadIdx.x;
    if (e >= N_EDGES) return;
    atomicAdd(&g_cnt[__ldg(rows + e)], 1);
}

// ---------------------------------------------------------------------------
// CSR build step 2a: per-block sums of counts
// ---------------------------------------------------------------------------
__global__ void k_scan1() {
    __shared__ int sh[TB];
    int i = blockIdx.x * TB + threadIdx.x;
    int c = (i < N_NODES) ? g_cnt[i] : 0;
    sh[threadIdx.x] = c; __syncthreads();
    for (int off = TB / 2; off > 0; off >>= 1) {
        if (threadIdx.x < off) sh[threadIdx.x] += sh[threadIdx.x + off];
        __syncthreads();
    }
    if (threadIdx.x == 0) g_bsum[blockIdx.x] = sh[0];
}

// ---------------------------------------------------------------------------
// CSR build step 2b: exclusive scan of block sums (single block)
// ---------------------------------------------------------------------------
__global__ void k_scan2() {
    __shared__ int sh[1024];
    int t = threadIdx.x;
    int v = (t < NBLK) ? g_bsum[t] : 0;
    sh[t] = v; __syncthreads();
    for (int off = 1; off < 1024; off <<= 1) {
        int add = (t >= off) ? sh[t - off] : 0;
        __syncthreads();
        sh[t] += add;
        __syncthreads();
    }
    if (t < NBLK) g_bsum[t] = sh[t] - v;   // exclusive
}

// ---------------------------------------------------------------------------
// CSR build step 2c: per-block exclusive scan + base -> row_ptr, fill cursors
// ---------------------------------------------------------------------------
__global__ void k_scan3() {
    __shared__ int sh[TB];
    int i = blockIdx.x * TB + threadIdx.x;
    int c = (i < N_NODES) ? g_cnt[i] : 0;
    sh[threadIdx.x] = c; __syncthreads();
    for (int off = 1; off < TB; off <<= 1) {
        int add = (threadIdx.x >= off) ? sh[threadIdx.x - off] : 0;
        __syncthreads();
        sh[threadIdx.x] += add;
        __syncthreads();
    }
    int excl = sh[threadIdx.x] - c + g_bsum[blockIdx.x];
    if (i < N_NODES) { g_rowptr[i] = excl; g_fill[i] = excl; }
    if (i == 0) g_rowptr[N_NODES] = N_EDGES;
}

// ---------------------------------------------------------------------------
// CSR build step 3: permute (col, val) into row-grouped order (6 B/edge)
// ---------------------------------------------------------------------------
__global__ void k_permute(const int*   __restrict__ rows,
                          const int*   __restrict__ cols,
                          const float* __restrict__ vals) {
    int e = blockIdx.x * blockDim.x + threadIdx.x;
    if (e >= N_EDGES) return;
    int r = __ldg(rows + e);
    int idx = atomicAdd(&g_fill[r], 1);
    g_pcol[idx] = __ldg(cols + e);
    g_pval[idx] = __float2half_rn(__ldg(vals + e));
}

// ---------------------------------------------------------------------------
// layer: one warp per row, atomic-free pull.
//   t[row] = sum val_e * src[col_e]   (fp16 gather, fp32 accumulate)
//   if APPLY_POP: t *= pop_inv[row]
//   dst[row] = fp16(t)
// Each lane owns 2 floats (half2 = 4B; 32 lanes = 128B fp16 row).
// ---------------------------------------------------------------------------
template <int APPLY_POP>
__global__ void k_layer(const __half* __restrict__ src,
                        __half*       __restrict__ dst,
                        const float*  __restrict__ upi,
                        const float*  __restrict__ ipi) {
    int gid  = blockIdx.x * blockDim.x + threadIdx.x;
    int row  = gid >> 5;
    int lane = gid & 31;
    if (row >= N_NODES) return;

    int beg = __ldg(&g_rowptr[row]);
    int end = __ldg(&g_rowptr[row + 1]);

    float2 s = make_float2(0.f, 0.f);
    for (int base = beg; base < end; base += 32) {
        int n = min(32, end - base);
        int   cv = 0;
        float vv = 0.f;
        if (lane < n) {
            cv = __ldg(&g_pcol[base + lane]);
            vv = __half2float(g_pval[base + lane]);
        }
        for (int j = 0; j < n; j++) {
            int   c = __shfl_sync(0xffffffffu, cv, j);
            float v = __shfl_sync(0xffffffffu, vv, j);
            half2 xh = *(const half2*)(src + (size_t)c * EMB + lane * 2);
            float2 x = __half22float2(xh);
            s.x = fmaf(v, x.x, s.x);
            s.y = fmaf(v, x.y, s.y);
        }
    }

    if (APPLY_POP) {
        float sc = (row < N_USER) ? __ldg(upi + row) : __ldg(ipi + (row - N_USER));
        s.x *= sc; s.y *= sc;
    }

    ((half2*)dst)[(size_t)row * 32 + lane] = __floats2half2_rn(s.x, s.y);
}

// ---------------------------------------------------------------------------
// gather A: sections 0-2, out[sec][b] = 0.25*(emb + pw*(c1+c2+c3))
// one thread per float2: 3*BATCH*32 threads
// ---------------------------------------------------------------------------
__global__ void k_gatherA(const float* __restrict__ ue,
                          const float* __restrict__ ie,
                          const float* __restrict__ pwp,
                          const int*   __restrict__ users,
                          const int*   __restrict__ pos,
                          const int*   __restrict__ neg,
                          float* __restrict__ out) {
    int gid = blockIdx.x * blockDim.x + threadIdx.x;
    const int per_sec = BATCH * 32;
    if (gid >= 3 * per_sec) return;
    int sec  = gid / per_sec;
    int rem  = gid - sec * per_sec;
    int b    = rem >> 5;
    int lane = rem & 31;

    int node; const float* emb;
    if (sec == 0)      { int u = __ldg(users + b); node = u;          emb = ue + (size_t)u * EMB; }
    else if (sec == 1) { int p = __ldg(pos + b);   node = N_USER + p; emb = ie + (size_t)p * EMB; }
    else               { int p = __ldg(neg + b);   node = N_USER + p; emb = ie + (size_t)p * EMB; }

    float pw = __ldg(pwp);
    size_t off = (size_t)node * 32 + lane;
    float2 e  = ((const float2*)emb)[lane];
    float2 c1 = __half22float2(((const half2*)g_c1)[off]);
    float2 c2 = __half22float2(((const half2*)g_c2)[off]);
    float2 c3 = __half22float2(((const half2*)g_c3)[off]);

    float2 o;
    o.x = PW_INV_LAYERS * (e.x + pw * (c1.x + c2.x + c3.x));
    o.y = PW_INV_LAYERS * (e.y + pw * (c1.y + c2.y + c3.y));
    // out is 6 sections of BATCH*EMB floats; sections 0-2 at the front
    ((float2*)out)[(size_t)sec * BATCH * 32 + rem] = o;
}

// ---------------------------------------------------------------------------
// gather B: sections 3-5, raw embedding gathers (fp32, float4 per thread)
// ---------------------------------------------------------------------------
__global__ void k_gatherB(const float* __restrict__ ue,
                          const float* __restrict__ ie,
                          const int*   __restrict__ users,
                          const int*   __restrict__ pos,
                          const int*   __restrict__ neg,
                          float* __restrict__ out) {
    int gid = blockIdx.x * blockDim.x + threadIdx.x;
    const int per_sec = BATCH * 16;
    if (gid >= 3 * per_sec) return;
    int sec = gid / per_sec;
    int rem = gid - sec * per_sec;
    int b   = rem >> 4;
    int p   = rem & 15;

    const float* src;
    if (sec == 0)      src = ue + (size_t)__ldg(users + b) * EMB;
    else if (sec == 1) src = ie + (size_t)__ldg(pos + b) * EMB;
    else               src = ie + (size_t)__ldg(neg + b) * EMB;

    // sections 3..5 start at offset 3*BATCH*EMB floats
    ((float4*)out)[(size_t)(3 + sec) * BATCH * 16 + rem] = ((const float4*)src)[p];
}

// ---------------------------------------------------------------------------
// kernel_launch
// Inputs: user_emb, item_emb, edge_rows, edge_cols, edge_vals,
//         user_pop_inv, item_pop_inv, popularity_weight, users, pos, neg
// ---------------------------------------------------------------------------
extern "C" void kernel_launch(void* const* d_in, const int* in_sizes, int n_in,
                              void* d_out, int out_size) {
    const float* ue    = (const float*)d_in[0];
    const float* ie    = (const float*)d_in[1];
    const int*   erow  = (const int*)  d_in[2];
    const int*   ecol  = (const int*)  d_in[3];
    const float* eval_ = (const float*)d_in[4];
    const float* upi   = (const float*)d_in[5];
    const float* ipi   = (const float*)d_in[6];
    const float* pwp   = (const float*)d_in[7];
    const int*   users = (const int*)  d_in[8];
    const int*   pos   = (const int*)  d_in[9];
    const int*   neg   = (const int*)  d_in[10];
    float* out = (float*)d_out;

    __half *c0, *c1, *c2, *c3;
    cudaGetSymbolAddress((void**)&c0, g_c0);
    cudaGetSymbolAddress((void**)&c1, g_c1);
    cudaGetSymbolAddress((void**)&c2, g_c2);
    cudaGetSymbolAddress((void**)&c3, g_c3);

    const int init_grid     = (N_NODES * 32 + TB - 1) / TB;
    const int edge_grid     = (N_EDGES + TB - 1) / TB;
    const int row_warp_grid = (N_NODES * 32 + TB - 1) / TB;   // 1 warp/row
    const int gathA_grid    = (3 * BATCH * 32 + TB - 1) / TB;
    const int gathB_grid    = (3 * BATCH * 16 + TB - 1) / TB;

    // init + CSR build (every replay; deterministic work)
    k_init<<<init_grid, TB>>>(ue, ie);
    k_hist<<<edge_grid, TB>>>(erow);
    k_scan1<<<NBLK, TB>>>();
    k_scan2<<<1, 1024>>>();
    k_scan3<<<NBLK, TB>>>();
    k_permute<<<edge_grid, TB>>>(erow, ecol, eval_);

    // 3 propagation layers, atomic-free, fp16 features
    k_layer<1><<<row_warp_grid, TB>>>(c0, c1, upi, ipi);
    k_layer<0><<<row_warp_grid, TB>>>(c1, c2, upi, ipi);
    k_layer<0><<<row_warp_grid, TB>>>(c2, c3, upi, ipi);

    k_gatherA<<<gathA_grid, TB>>>(ue, ie, pwp, users, pos, neg, out);
    k_gatherB<<<gathB_grid, TB>>>(ue, ie, users, pos, neg, out);

    (void)in_sizes; (void)n_in; (void)out_size;
}

// round 7
// speedup vs baseline: 3.1406x; 1.3516x over previous
#include <cuda_runtime.h>
#include <cuda_fp16.h>
#include <cstddef>

#define N_USER  100000
#define N_ITEM  50000
#define N_NODES 150000
#define EMB     64
#define N_EDGES 4000000
#define BATCH   4096
#define PW_INV_LAYERS 0.25f   // 1/(N_LAYERS+1)
#define TB 256
#define NBLK ((N_NODES + TB - 1) / TB)   // 586 scan blocks

// ---- device-global scratch (allocation-free) ----
// fp16 feature buffers: 150000*64*2B = 19.2 MB each (no c3 buffer needed)
__device__ __half g_c0[(size_t)N_NODES * EMB];
__device__ __half g_c1[(size_t)N_NODES * EMB];
__device__ __half g_c2[(size_t)N_NODES * EMB];
__device__ int    g_cnt   [N_NODES];        // zero-init; re-zeroed by k_scan3
__device__ int    g_fill  [N_NODES];
__device__ int    g_rowptr[N_NODES + 1];
__device__ int    g_bsum  [1024];
__device__ int2   g_perm  [N_EDGES];        // (col, val-as-fp32-bits) 32 MB

// ---------------------------------------------------------------------------
// init + hist fused:
//   threads < N_NODES*32: c0 = fp16(concat(user_emb, item_emb))  (half2 each)
//   threads < N_EDGES   : histogram of destination rows (g_cnt starts at 0:
//                         zero-init on first replay, re-zeroed by k_scan3)
// ---------------------------------------------------------------------------
__global__ void k_init_hist(const float* __restrict__ ue,
                            const float* __restrict__ ie,
                            const int*   __restrict__ rows) {
    int i = blockIdx.x * blockDim.x + threadIdx.x;
    if (i < N_EDGES)
        atomicAdd(&g_cnt[__ldg(rows + i)], 1);
    if (i < N_NODES * 32) {
        const float2* u2 = (const float2*)ue;
        const float2* i2 = (const float2*)ie;
        float2 v = (i < N_USER * 32) ? u2[i] : i2[i - N_USER * 32];
        ((half2*)g_c0)[i] = __floats2half2_rn(v.x, v.y);
    }
}

// ---------------------------------------------------------------------------
// CSR scan step a: per-block sums of counts
// ---------------------------------------------------------------------------
__global__ void k_scan1() {
    __shared__ int sh[TB];
    int i = blockIdx.x * TB + threadIdx.x;
    int c = (i < N_NODES) ? g_cnt[i] : 0;
    sh[threadIdx.x] = c; __syncthreads();
    for (int off = TB / 2; off > 0; off >>= 1) {
        if (threadIdx.x < off) sh[threadIdx.x] += sh[threadIdx.x + off];
        __syncthreads();
    }
    if (threadIdx.x == 0) g_bsum[blockIdx.x] = sh[0];
}

// ---------------------------------------------------------------------------
// CSR scan step b: exclusive scan of 586 block sums (single block)
// ---------------------------------------------------------------------------
__global__ void k_scan2() {
    __shared__ int sh[1024];
    int t = threadIdx.x;
    int v = (t < NBLK) ? g_bsum[t] : 0;
    sh[t] = v; __syncthreads();
    for (int off = 1; off < 1024; off <<= 1) {
        int add = (t >= off) ? sh[t - off] : 0;
        __syncthreads();
        sh[t] += add;
        __syncthreads();
    }
    if (t < NBLK) g_bsum[t] = sh[t] - v;   // exclusive
}

// ---------------------------------------------------------------------------
// CSR scan step c: per-block exclusive scan + base -> row_ptr, fill cursors.
// Also re-zeroes g_cnt (after reading) so the next replay's fused hist
// starts from a clean histogram.
// ---------------------------------------------------------------------------
__global__ void k_scan3() {
    __shared__ int sh[TB];
    int i = blockIdx.x * TB + threadIdx.x;
    int c = (i < N_NODES) ? g_cnt[i] : 0;
    sh[threadIdx.x] = c; __syncthreads();
    for (int off = 1; off < TB; off <<= 1) {
        int add = (threadIdx.x >= off) ? sh[threadIdx.x - off] : 0;
        __syncthreads();
        sh[threadIdx.x] += add;
        __syncthreads();
    }
    int excl = sh[threadIdx.x] - c + g_bsum[blockIdx.x];
    if (i < N_NODES) { g_rowptr[i] = excl; g_fill[i] = excl; g_cnt[i] = 0; }
    if (i == 0) g_rowptr[N_NODES] = N_EDGES;
}

// ---------------------------------------------------------------------------
// CSR build: permute (col, val) into row-grouped order, one 8B store/edge
// ---------------------------------------------------------------------------
__global__ void k_permute(const int*   __restrict__ rows,
                          const int*   __restrict__ cols,
                          const float* __restrict__ vals) {
    int e = blockIdx.x * blockDim.x + threadIdx.x;
    if (e >= N_EDGES) return;
    int r = __ldg(rows + e);
    int idx = atomicAdd(&g_fill[r], 1);
    g_perm[idx] = make_int2(__ldg(cols + e), __float_as_int(__ldg(vals + e)));
}

// ---------------------------------------------------------------------------
// full layer: one warp per row, atomic-free pull.
//   t[row] = sum val_e * src[col_e]   (fp16 gather, fp32 accumulate)
//   if APPLY_POP: t *= pop_inv[row]
//   dst[row] = fp16(t)
// ---------------------------------------------------------------------------
template <int APPLY_POP>
__global__ void k_layer(const __half* __restrict__ src,
                        __half*       __restrict__ dst,
                        const float*  __restrict__ upi,
                        const float*  __restrict__ ipi) {
    int gid  = blockIdx.x * blockDim.x + threadIdx.x;
    int row  = gid >> 5;
    int lane = gid & 31;
    if (row >= N_NODES) return;

    int beg = __ldg(&g_rowptr[row]);
    int end = __ldg(&g_rowptr[row + 1]);

    float2 s = make_float2(0.f, 0.f);
    for (int base = beg; base < end; base += 32) {
        int n = min(32, end - base);
        int2 ev = make_int2(0, 0);
        if (lane < n) ev = g_perm[base + lane];
        for (int j = 0; j < n; j++) {
            int   c = __shfl_sync(0xffffffffu, ev.x, j);
            float v = __int_as_float(__shfl_sync(0xffffffffu, ev.y, j));
            float2 x = __half22float2(*(const half2*)(src + (size_t)c * EMB + lane * 2));
            s.x = fmaf(v, x.x, s.x);
            s.y = fmaf(v, x.y, s.y);
        }
    }

    if (APPLY_POP) {
        float sc = (row < N_USER) ? __ldg(upi + row) : __ldg(ipi + (row - N_USER));
        s.x *= sc; s.y *= sc;
    }

    ((half2*)dst)[(size_t)row * 32 + lane] = __floats2half2_rn(s.x, s.y);
}

// ---------------------------------------------------------------------------
// fused layer-3 + gather: one warp per batch slot (3*BATCH warps).
// c3[node] is computed in registers from c2 (only the ~12K sampled rows!),
// then:
//   out[sec]   = 0.25*(emb + pw*(c1+c2+c3))    sec in 0..2
//   out[3+sec] = emb                            raw embedding sections
// ---------------------------------------------------------------------------
__global__ void k_l3_gather(const float* __restrict__ ue,
                            const float* __restrict__ ie,
                            const float* __restrict__ pwp,
                            const int*   __restrict__ users,
                            const int*   __restrict__ pos,
                            const int*   __restrict__ neg,
                            float* __restrict__ out) {
    int gid  = blockIdx.x * blockDim.x + threadIdx.x;
    int w    = gid >> 5;               // 0 .. 3*BATCH-1
    int lane = gid & 31;
    if (w >= 3 * BATCH) return;
    int sec = w / BATCH;
    int b   = w - sec * BATCH;

    int node; const float* emb;
    if (sec == 0)      { int u = __ldg(users + b); node = u;          emb = ue + (size_t)u * EMB; }
    else if (sec == 1) { int p = __ldg(pos + b);   node = N_USER + p; emb = ie + (size_t)p * EMB; }
    else               { int p = __ldg(neg + b);   node = N_USER + p; emb = ie + (size_t)p * EMB; }

    // compute c3[node] (lane's float2 slice) from c2
    int beg = __ldg(&g_rowptr[node]);
    int end = __ldg(&g_rowptr[node + 1]);
    float2 s = make_float2(0.f, 0.f);
    for (int base = beg; base < end; base += 32) {
        int n = min(32, end - base);
        int2 ev = make_int2(0, 0);
        if (lane < n) ev = g_perm[base + lane];
        for (int j = 0; j < n; j++) {
            int   c = __shfl_sync(0xffffffffu, ev.x, j);
            float v = __int_as_float(__shfl_sync(0xffffffffu, ev.y, j));
            float2 x = __half22float2(*(const half2*)(g_c2 + (size_t)c * EMB + lane * 2));
            s.x = fmaf(v, x.x, s.x);
            s.y = fmaf(v, x.y, s.y);
        }
    }

    float pw = __ldg(pwp);
    size_t off = (size_t)node * 32 + lane;
    float2 e  = ((const float2*)emb)[lane];
    float2 c1 = __half22float2(((const half2*)g_c1)[off]);
    float2 c2 = __half22float2(((const half2*)g_c2)[off]);

    float2 o;
    o.x = PW_INV_LAYERS * (e.x + pw * (c1.x + c2.x + s.x));
    o.y = PW_INV_LAYERS * (e.y + pw * (c1.y + c2.y + s.y));

    size_t slot = (size_t)b * 32 + lane;
    ((float2*)out)[(size_t)sec * BATCH * 32 + slot]       = o;   // sections 0-2
    ((float2*)out)[(size_t)(3 + sec) * BATCH * 32 + slot] = e;   // sections 3-5
}

// ---------------------------------------------------------------------------
// kernel_launch
// Inputs: user_emb, item_emb, edge_rows, edge_cols, edge_vals,
//         user_pop_inv, item_pop_inv, popularity_weight, users, pos, neg
// ---------------------------------------------------------------------------
extern "C" void kernel_launch(void* const* d_in, const int* in_sizes, int n_in,
                              void* d_out, int out_size) {
    const float* ue    = (const float*)d_in[0];
    const float* ie    = (const float*)d_in[1];
    const int*   erow  = (const int*)  d_in[2];
    const int*   ecol  = (const int*)  d_in[3];
    const float* eval_ = (const float*)d_in[4];
    const float* upi   = (const float*)d_in[5];
    const float* ipi   = (const float*)d_in[6];
    const float* pwp   = (const float*)d_in[7];
    const int*   users = (const int*)  d_in[8];
    const int*   pos   = (const int*)  d_in[9];
    const int*   neg   = (const int*)  d_in[10];
    float* out = (float*)d_out;

    __half *c0, *c1, *c2;
    cudaGetSymbolAddress((void**)&c0, g_c0);
    cudaGetSymbolAddress((void**)&c1, g_c1);
    cudaGetSymbolAddress((void**)&c2, g_c2);

    const int inith_grid    = (N_NODES * 32 + TB - 1) / TB;   // covers 4M too
    const int edge_grid     = (N_EDGES + TB - 1) / TB;
    const int row_warp_grid = (N_NODES * 32 + TB - 1) / TB;   // 1 warp/row
    const int l3g_grid      = (3 * BATCH * 32 + TB - 1) / TB;

    // init + CSR build (every replay; deterministic)
    k_init_hist<<<inith_grid, TB>>>(ue, ie, erow);
    k_scan1<<<NBLK, TB>>>();
    k_scan2<<<1, 1024>>>();
    k_scan3<<<NBLK, TB>>>();
    k_permute<<<edge_grid, TB>>>(erow, ecol, eval_);

    // layers 1 and 2 over all nodes (atomic-free pull, fp16 features)
    k_layer<1><<<row_warp_grid, TB>>>(c0, c1, upi, ipi);
    k_layer<0><<<row_warp_grid, TB>>>(c1, c2, upi, ipi);

    // layer 3 restricted to sampled rows, fused with output gather
    k_l3_gather<<<l3g_grid, TB>>>(ue, ie, pwp, users, pos, neg, out);

    (void)in_sizes; (void)n_in; (void)out_size;
}

// round 8
// speedup vs baseline: 3.3755x; 1.0748x over previous
#include <cuda_runtime.h>
#include <cuda_fp16.h>
#include <cstddef>

#define N_USER  100000
#define N_ITEM  50000
#define N_NODES 150000
#define EMB     64
#define N_EDGES 4000000
#define BATCH   4096
#define PW_INV_LAYERS 0.25f   // 1/(N_LAYERS+1)
#define TB 256
#define NBLK ((N_NODES + TB - 1) / TB)   // 586 scan blocks

// ---- device-global scratch (allocation-free) ----
__device__ __half g_c0[(size_t)N_NODES * EMB];
__device__ __half g_c1[(size_t)N_NODES * EMB];
__device__ __half g_c2[(size_t)N_NODES * EMB];
__device__ int    g_cnt   [N_NODES];        // zero-init; re-zeroed by k_scan3
__device__ int    g_fill  [N_NODES];
__device__ int    g_rowptr[N_NODES + 1];
__device__ int    g_bsum  [1024];
__device__ int2   g_perm  [N_EDGES];        // (col, val-as-fp32-bits) 32 MB

// ---------------------------------------------------------------------------
// init + hist fused
// ---------------------------------------------------------------------------
__global__ void k_init_hist(const float* __restrict__ ue,
                            const float* __restrict__ ie,
                            const int*   __restrict__ rows) {
    int i = blockIdx.x * blockDim.x + threadIdx.x;
    if (i < N_EDGES)
        atomicAdd(&g_cnt[__ldg(rows + i)], 1);
    if (i < N_NODES * 32) {
        const float2* u2 = (const float2*)ue;
        const float2* i2 = (const float2*)ie;
        float2 v = (i < N_USER * 32) ? u2[i] : i2[i - N_USER * 32];
        ((half2*)g_c0)[i] = __floats2half2_rn(v.x, v.y);
    }
}

// ---------------------------------------------------------------------------
// CSR scan a: per-block sums
// ---------------------------------------------------------------------------
__global__ void k_scan1() {
    __shared__ int sh[TB];
    int i = blockIdx.x * TB + threadIdx.x;
    int c = (i < N_NODES) ? g_cnt[i] : 0;
    sh[threadIdx.x] = c; __syncthreads();
    for (int off = TB / 2; off > 0; off >>= 1) {
        if (threadIdx.x < off) sh[threadIdx.x] += sh[threadIdx.x + off];
        __syncthreads();
    }
    if (threadIdx.x == 0) g_bsum[blockIdx.x] = sh[0];
}

// ---------------------------------------------------------------------------
// CSR scan b: exclusive scan of block sums (single block)
// ---------------------------------------------------------------------------
__global__ void k_scan2() {
    __shared__ int sh[1024];
    int t = threadIdx.x;
    int v = (t < NBLK) ? g_bsum[t] : 0;
    sh[t] = v; __syncthreads();
    for (int off = 1; off < 1024; off <<= 1) {
        int add = (t >= off) ? sh[t - off] : 0;
        __syncthreads();
        sh[t] += add;
        __syncthreads();
    }
    if (t < NBLK) g_bsum[t] = sh[t] - v;   // exclusive
}

// ---------------------------------------------------------------------------
// CSR scan c: row_ptr + fill cursors; re-zeroes g_cnt for next replay
// ---------------------------------------------------------------------------
__global__ void k_scan3() {
    __shared__ int sh[TB];
    int i = blockIdx.x * TB + threadIdx.x;
    int c = (i < N_NODES) ? g_cnt[i] : 0;
    sh[threadIdx.x] = c; __syncthreads();
    for (int off = 1; off < TB; off <<= 1) {
        int add = (threadIdx.x >= off) ? sh[threadIdx.x - off] : 0;
        __syncthreads();
        sh[threadIdx.x] += add;
        __syncthreads();
    }
    int excl = sh[threadIdx.x] - c + g_bsum[blockIdx.x];
    if (i < N_NODES) { g_rowptr[i] = excl; g_fill[i] = excl; g_cnt[i] = 0; }
    if (i == 0) g_rowptr[N_NODES] = N_EDGES;
}

// ---------------------------------------------------------------------------
// CSR build: permute (col, val) into row-grouped order
// ---------------------------------------------------------------------------
__global__ void k_permute(const int*   __restrict__ rows,
                          const int*   __restrict__ cols,
                          const float* __restrict__ vals) {
    int e = blockIdx.x * blockDim.x + threadIdx.x;
    if (e >= N_EDGES) return;
    int r = __ldg(rows + e);
    int idx = atomicAdd(&g_fill[r], 1);
    g_perm[idx] = make_int2(__ldg(cols + e), __float_as_int(__ldg(vals + e)));
}

// ---------------------------------------------------------------------------
// Warp-level row accumulation core:
// - warp loads up to 32 (col,val) entries coalesced, stages them in its smem
//   slab, then runs a FIXED 32-trip fully-unrolled loop reading entries via
//   broadcast LDS (no shfl chains) -> 32 independent gather LDGs in flight.
// - inactive entries are (col=0, val=0): they gather row 0 with weight 0,
//   which is harmless and L1-hot.
// ---------------------------------------------------------------------------
__device__ __forceinline__ float2 row_accumulate(const __half* __restrict__ src,
                                                 int beg, int end, int lane,
                                                 int2* __restrict__ slab) {
    float2 s = make_float2(0.f, 0.f);
    for (int base = beg; base < end; base += 32) {
        int n = end - base;                    // may exceed 32; clamp by pred
        int2 ev = make_int2(0, 0);
        if (lane < n) ev = __ldg(&g_perm[base + lane]);
        __syncwarp();
        slab[lane] = ev;
        __syncwarp();
        #pragma unroll
        for (int j = 0; j < 32; j++) {
            int2  e = slab[j];
            float v = __int_as_float(e.y);
            float2 x = __half22float2(
                *(const half2*)(src + (size_t)e.x * EMB + lane * 2));
            s.x = fmaf(v, x.x, s.x);
            s.y = fmaf(v, x.y, s.y);
        }
    }
    return s;
}

// ---------------------------------------------------------------------------
// full layer: one warp per row, atomic-free pull (fp16 in, fp32 accum)
// ---------------------------------------------------------------------------
template <int APPLY_POP>
__global__ void __launch_bounds__(TB)
k_layer(const __half* __restrict__ src,
        __half*       __restrict__ dst,
        const float*  __restrict__ upi,
        const float*  __restrict__ ipi) {
    __shared__ int2 sh[TB / 32][32];
    int gid  = blockIdx.x * blockDim.x + threadIdx.x;
    int row  = gid >> 5;
    int lane = gid & 31;
    int wid  = threadIdx.x >> 5;
    if (row >= N_NODES) return;

    int beg = __ldg(&g_rowptr[row]);
    int end = __ldg(&g_rowptr[row + 1]);

    float2 s = row_accumulate(src, beg, end, lane, sh[wid]);

    if (APPLY_POP) {
        float sc = (row < N_USER) ? __ldg(upi + row) : __ldg(ipi + (row - N_USER));
        s.x *= sc; s.y *= sc;
    }

    ((half2*)dst)[(size_t)row * 32 + lane] = __floats2half2_rn(s.x, s.y);
}

// ---------------------------------------------------------------------------
// fused layer-3 + gather: one warp per batch slot (3*BATCH warps).
// c3[node] computed in registers from c2 (only ~12K sampled rows), then:
//   out[sec]   = 0.25*(emb + pw*(c1+c2+c3))   sec 0..2
//   out[3+sec] = emb                           raw embedding sections
// ---------------------------------------------------------------------------
__global__ void __launch_bounds__(TB)
k_l3_gather(const float* __restrict__ ue,
            const float* __restrict__ ie,
            const float* __restrict__ pwp,
            const int*   __restrict__ users,
            const int*   __restrict__ pos,
            const int*   __restrict__ neg,
            float* __restrict__ out) {
    __shared__ int2 sh[TB / 32][32];
    int gid  = blockIdx.x * blockDim.x + threadIdx.x;
    int w    = gid >> 5;               // 0 .. 3*BATCH-1
    int lane = gid & 31;
    int wid  = threadIdx.x >> 5;
    if (w >= 3 * BATCH) return;
    int sec = w / BATCH;
    int b   = w - sec * BATCH;

    int node; const float* emb;
    if (sec == 0)      { int u = __ldg(users + b); node = u;          emb = ue + (size_t)u * EMB; }
    else if (sec == 1) { int p = __ldg(pos + b);   node = N_USER + p; emb = ie + (size_t)p * EMB; }
    else               { int p = __ldg(neg + b);   node = N_USER + p; emb = ie + (size_t)p * EMB; }

    int beg = __ldg(&g_rowptr[node]);
    int end = __ldg(&g_rowptr[node + 1]);
    float2 s = row_accumulate(g_c2, beg, end, lane, sh[wid]);

    float pw = __ldg(pwp);
    size_t off = (size_t)node * 32 + lane;
    float2 e  = ((const float2*)emb)[lane];
    float2 c1 = __half22float2(((const half2*)g_c1)[off]);
    float2 c2 = __half22float2(((const half2*)g_c2)[off]);

    float2 o;
    o.x = PW_INV_LAYERS * (e.x + pw * (c1.x + c2.x + s.x));
    o.y = PW_INV_LAYERS * (e.y + pw * (c1.y + c2.y + s.y));

    size_t slot = (size_t)b * 32 + lane;
    ((float2*)out)[(size_t)sec * BATCH * 32 + slot]       = o;   // sections 0-2
    ((float2*)out)[(size_t)(3 + sec) * BATCH * 32 + slot] = e;   // sections 3-5
}

// ---------------------------------------------------------------------------
// kernel_launch
// Inputs: user_emb, item_emb, edge_rows, edge_cols, edge_vals,
//         user_pop_inv, item_pop_inv, popularity_weight, users, pos, neg
// ---------------------------------------------------------------------------
extern "C" void kernel_launch(void* const* d_in, const int* in_sizes, int n_in,
                              void* d_out, int out_size) {
    const float* ue    = (const float*)d_in[0];
    const float* ie    = (const float*)d_in[1];
    const int*   erow  = (const int*)  d_in[2];
    const int*   ecol  = (const int*)  d_in[3];
    const float* eval_ = (const float*)d_in[4];
    const float* upi   = (const float*)d_in[5];
    const float* ipi   = (const float*)d_in[6];
    const float* pwp   = (const float*)d_in[7];
    const int*   users = (const int*)  d_in[8];
    const int*   pos   = (const int*)  d_in[9];
    const int*   neg   = (const int*)  d_in[10];
    float* out = (float*)d_out;

    __half *c0, *c1, *c2;
    cudaGetSymbolAddress((void**)&c0, g_c0);
    cudaGetSymbolAddress((void**)&c1, g_c1);
    cudaGetSymbolAddress((void**)&c2, g_c2);

    const int inith_grid    = (N_NODES * 32 + TB - 1) / TB;   // covers 4M too
    const int edge_grid     = (N_EDGES + TB - 1) / TB;
    const int row_warp_grid = (N_NODES * 32 + TB - 1) / TB;   // 1 warp/row
    const int l3g_grid      = (3 * BATCH * 32 + TB - 1) / TB;

    // init + CSR build (every replay; deterministic)
    k_init_hist<<<inith_grid, TB>>>(ue, ie, erow);
    k_scan1<<<NBLK, TB>>>();
    k_scan2<<<1, 1024>>>();
    k_scan3<<<NBLK, TB>>>();
    k_permute<<<edge_grid, TB>>>(erow, ecol, eval_);

    // layers 1 and 2 over all nodes (atomic-free pull, fp16 features)
    k_layer<1><<<row_warp_grid, TB>>>(c0, c1, upi, ipi);
    k_layer<0><<<row_warp_grid, TB>>>(c1, c2, upi, ipi);

    // layer 3 restricted to sampled rows, fused with output gather
    k_l3_gather<<<l3g_grid, TB>>>(ue, ie, pwp, users, pos, neg, out);

    (void)in_sizes; (void)n_in; (void)out_size;
}